// round 1
// baseline (speedup 1.0000x reference)
#include <cuda_runtime.h>

// 8-qubit batched circuit simulator, warp-per-element.
// k = lane*8 + j ; wire w <-> bit (7-w) of k.
//   wires 0..4 -> lane bits 4..0 ; wires 5..7 -> j bits 2..0.

#define NQ 8
#define DIM 256
#define WPB 8                 // warps per block
#define THREADS (WPB * 32)
#define FULL 0xffffffffu

__global__ __launch_bounds__(THREADS)
void qsim_kernel(const float* __restrict__ x,
                 const float* __restrict__ theta,
                 float* __restrict__ out, int B)
{
    __shared__ float2 gsm[2][8][4];        // Rot gate matrices [layer][wire][g00,g01,g10,g11]
    __shared__ unsigned char perm[2][256]; // composed CNOT-ring permutations
    __shared__ float2 stage[WPB][256];     // per-warp permutation staging

    const int tid = threadIdx.x;

    // ---- precompute gate matrices (16 threads) ----
    if (tid < 16) {
        int l = tid >> 3, w = tid & 7;
        const float* t = theta + (l * 8 + w) * 3;
        float phi = t[0], th = t[1], om = t[2];
        float s, c;   sincosf(0.5f * th,        &s,  &c);
        float sa, ca; sincosf(0.5f * (phi + om), &sa, &ca);
        float sb, cb; sincosf(0.5f * (phi - om), &sb, &cb);
        // g00 = e^{-i(phi+om)/2} c ; g01 = -e^{+i(phi-om)/2} s
        // g10 = e^{-i(phi-om)/2} s ; g11 = e^{+i(phi+om)/2} c
        gsm[l][w][0] = make_float2( ca * c, -sa * c);
        gsm[l][w][1] = make_float2(-cb * s, -sb * s);
        gsm[l][w][2] = make_float2( cb * s, -sb * s);
        gsm[l][w][3] = make_float2( ca * c,  sa * c);
    }

    // ---- precompute ring permutations (256 threads) ----
    // s_after[k] = s_before[L1(L2(...L8(k)))], CNOT i: ctrl=w=i-1, tgt=(w+r)%8
    // L_w(m) = m XOR (bit_{7-w}(m) << (7-((w+r)%8)))
    {
        for (int ring = 0; ring < 2; ring++) {
            int r = ring + 1;
            int m = tid;
            for (int w = 7; w >= 0; w--) {
                int pc = 7 - w;
                int pt = 7 - ((w + r) & 7);
                m ^= ((m >> pc) & 1) << pt;
            }
            perm[ring][tid] = (unsigned char)m;
        }
    }
    __syncthreads();

    const int warp = tid >> 5;
    const int lane = tid & 31;
    const int e = blockIdx.x * WPB + warp;
    if (e >= B) return;   // whole warp exits together

    // ---- embedding: product state from RX angles ----
    float xv = x[e * 8 + (lane & 7)];
    float sv, cv;
    sincosf(0.5f * xv, &sv, &cv);
    float cw[8], sw[8];
#pragma unroll
    for (int w = 0; w < 8; w++) {
        cw[w] = __shfl_sync(FULL, cv, w);
        sw[w] = __shfl_sync(FULL, sv, w);
    }
    float ml = 1.f;
#pragma unroll
    for (int w = 0; w < 5; w++)
        ml *= ((lane >> (4 - w)) & 1) ? sw[w] : cw[w];
    const int pl = __popc(lane);

    float ar[8], ai[8];
#pragma unroll
    for (int j = 0; j < 8; j++) {
        float m = ml * ((j & 4) ? sw[5] : cw[5])
                     * ((j & 2) ? sw[6] : cw[6])
                     * ((j & 1) ? sw[7] : cw[7]);
        int p = (pl + __popc(j)) & 3;   // (-i)^p phase
        ar[j] = (p == 0) ? m : ((p == 2) ? -m : 0.f);
        ai[j] = (p == 1) ? -m : ((p == 3) ? m : 0.f);
    }

    // ---- two entangling layers ----
#pragma unroll
    for (int layer = 0; layer < 2; layer++) {
#pragma unroll
        for (int w = 0; w < 8; w++) {
            const float2 g00 = gsm[layer][w][0];
            const float2 g01 = gsm[layer][w][1];
            const float2 g10 = gsm[layer][w][2];
            const float2 g11 = gsm[layer][w][3];
            if (w < 5) {
                // wire lives in lane bits -> shuffle butterfly
                const int lm  = 1 << (4 - w);
                const int myb = (lane >> (4 - w)) & 1;
                const float gr = myb ? g11.x : g00.x;
                const float gi = myb ? g11.y : g00.y;
                const float hr = myb ? g10.x : g01.x;
                const float hi = myb ? g10.y : g01.y;
#pragma unroll
                for (int j = 0; j < 8; j++) {
                    float orr = __shfl_xor_sync(FULL, ar[j], lm);
                    float oii = __shfl_xor_sync(FULL, ai[j], lm);
                    float nr = gr * ar[j] - gi * ai[j] + hr * orr - hi * oii;
                    float ni = gr * ai[j] + gi * ar[j] + hr * oii + hi * orr;
                    ar[j] = nr; ai[j] = ni;
                }
            } else {
                // wire lives in register bits -> local butterfly
                const int bm = 1 << (7 - w);   // 4, 2, 1
#pragma unroll
                for (int j0 = 0; j0 < 8; j0++) {
                    if (j0 & bm) continue;
                    int j1 = j0 | bm;
                    float a_r = ar[j0], a_i = ai[j0];
                    float b_r = ar[j1], b_i = ai[j1];
                    ar[j0] = g00.x * a_r - g00.y * a_i + g01.x * b_r - g01.y * b_i;
                    ai[j0] = g00.x * a_i + g00.y * a_r + g01.x * b_i + g01.y * b_r;
                    ar[j1] = g10.x * a_r - g10.y * a_i + g11.x * b_r - g11.y * b_i;
                    ai[j1] = g10.x * a_i + g10.y * a_r + g11.x * b_i + g11.y * b_r;
                }
            }
        }
        // ---- CNOT ring as one permutation via smem staging ----
#pragma unroll
        for (int j = 0; j < 8; j++)
            stage[warp][j * 32 + lane] = make_float2(ar[j], ai[j]);
        __syncwarp();
#pragma unroll
        for (int j = 0; j < 8; j++) {
            int k  = lane * 8 + j;
            int kp = perm[layer][k];
            float2 v = stage[warp][(kp & 7) * 32 + (kp >> 3)];
            ar[j] = v.x; ai[j] = v.y;
        }
        __syncwarp();
    }

    // ---- expval(Z0): sign by bit7 of k = bit4 of lane ----
    float acc = 0.f;
#pragma unroll
    for (int j = 0; j < 8; j++)
        acc += ar[j] * ar[j] + ai[j] * ai[j];
    if (lane & 16) acc = -acc;
#pragma unroll
    for (int off = 16; off; off >>= 1)
        acc += __shfl_down_sync(FULL, acc, off);
    if (lane == 0) out[e] = (acc + 1.f) * 0.5f;
}

extern "C" void kernel_launch(void* const* d_in, const int* in_sizes, int n_in,
                              void* d_out, int out_size)
{
    const float* x     = (const float*)d_in[0];
    const float* theta = (const float*)d_in[1];
    // defensive: theta has 48 elements, x has B*8
    if (n_in >= 2 && in_sizes[0] == 48) {
        const float* tmp = x; x = theta; theta = tmp;
    }
    int B = out_size;  // one output per element
    int blocks = (B + WPB - 1) / WPB;
    qsim_kernel<<<blocks, THREADS>>>(x, theta, (float*)d_out, B);
}